// round 2
// baseline (speedup 1.0000x reference)
#include <cuda_runtime.h>
#include <cmath>

// Problem dims (fixed per reference)
#define T_DIM 512
#define N_DIM 1024
#define D_DIM 256
#define TN    (T_DIM * N_DIM)          // 524288 flattened rows
#define BM    64                        // row tile for score GEMM
#define BK    32                        // k tile

// ---------------- device scratch (static, no allocations) ----------------
__device__ float g_e [TN];              // scores e[t*N + n]
__device__ float g_a [TN];              // recurrence coeff a_t
__device__ float g_b [TN];              // recurrence coeff b_t
__device__ float g_wt[D_DIM * D_DIM];   // fc_w transposed: wt[k*256 + e] = fc_w[e*256 + k]

// ---------------- kernel 0: transpose fc_w (256x256) ----------------
__global__ void k_transpose(const float* __restrict__ w) {
    __shared__ float tile[32][33];
    int bx = blockIdx.x;   // k-block
    int by = blockIdx.y;   // e-block
    int tx = threadIdx.x;  // 0..31
    int ty = threadIdx.y;  // 0..7
    #pragma unroll
    for (int i = 0; i < 32; i += 8) {
        // read w[e][k], e = by*32+ty+i, k = bx*32+tx  (coalesced)
        tile[ty + i][tx] = w[(by * 32 + ty + i) * D_DIM + bx * 32 + tx];
    }
    __syncthreads();
    #pragma unroll
    for (int i = 0; i < 32; i += 8) {
        // write wt[k][e], k = bx*32+ty+i, e = by*32+tx (coalesced)
        g_wt[(bx * 32 + ty + i) * D_DIM + by * 32 + tx] = tile[tx][ty + i];
    }
}

// accurate tanh that fast-math cannot degrade below ~1e-6 rel
__device__ __forceinline__ float tanh_acc(float x) {
    float ex = __expf(2.0f * x);        // exp(2x); inf / 0 at extremes is fine
    return 1.0f - 2.0f / (ex + 1.0f);   // -> +-1 correctly at saturation
}

// ---------------- kernel 1: e = score_w . tanh(H @ fc_w^T + fc_b) ----------------
// Grid: TN/BM blocks of 256 threads. Each block: BM=64 rows x all 256 output cols.
__global__ __launch_bounds__(256, 2) void k_score(
    const float* __restrict__ H,
    const float* __restrict__ fc_b,
    const float* __restrict__ score_w)
{
    __shared__ float As[BM][BK + 4];     // [row][k], padded for aligned float4 stores
    __shared__ float Ws[BK][D_DIM];      // [k][e], e contiguous -> conflict-free reads

    const int m0  = blockIdx.x * BM;
    const int tid = threadIdx.x;
    const int tx  = tid & 31;            // lane: covers 8 output cols tx*8..tx*8+7
    const int ty  = tid >> 5;            // warp: covers 8 rows ty*8..ty*8+7

    float acc[8][8];
    #pragma unroll
    for (int i = 0; i < 8; ++i)
        #pragma unroll
        for (int j = 0; j < 8; ++j) acc[i][j] = 0.0f;

    for (int k0 = 0; k0 < D_DIM; k0 += BK) {
        // load A tile: 64 rows x 32 k = 512 float4, 2 per thread
        #pragma unroll
        for (int l = 0; l < 2; ++l) {
            int f  = tid + l * 256;
            int r  = f >> 3;             // 8 float4 per row
            int c4 = f & 7;
            float4 v = *(const float4*)&H[(m0 + r) * D_DIM + k0 + c4 * 4];
            *(float4*)&As[r][c4 * 4] = v;
        }
        // load W tile from transposed weights: Ws[kk][e] = wt[(k0+kk)*256 + e]
        #pragma unroll
        for (int l = 0; l < 8; ++l) {
            int f  = tid + l * 256;
            int kk = f >> 6;             // 64 float4 per k-row
            int e4 = f & 63;
            *(float4*)&Ws[kk][e4 * 4] = *(const float4*)&g_wt[(k0 + kk) * D_DIM + e4 * 4];
        }
        __syncthreads();

        #pragma unroll
        for (int kk = 0; kk < BK; ++kk) {
            float a[8], w[8];
            #pragma unroll
            for (int i = 0; i < 8; ++i) a[i] = As[ty * 8 + i][kk];   // warp-broadcast
            #pragma unroll
            for (int j = 0; j < 8; ++j) w[j] = Ws[kk][tx * 8 + j];
            #pragma unroll
            for (int i = 0; i < 8; ++i)
                #pragma unroll
                for (int j = 0; j < 8; ++j)
                    acc[i][j] = fmaf(a[i], w[j], acc[i][j]);
        }
        __syncthreads();
    }

    // epilogue: tanh(+bias) dot score_w, warp-reduce across the 32 lanes (cols)
    float bias[8], sw[8];
    #pragma unroll
    for (int j = 0; j < 8; ++j) {
        bias[j] = fc_b[tx * 8 + j];
        sw[j]   = score_w[tx * 8 + j];
    }
    #pragma unroll
    for (int i = 0; i < 8; ++i) {
        float s = 0.0f;
        #pragma unroll
        for (int j = 0; j < 8; ++j)
            s = fmaf(tanh_acc(acc[i][j] + bias[j]), sw[j], s);
        #pragma unroll
        for (int off = 16; off > 0; off >>= 1)
            s += __shfl_down_sync(0xFFFFFFFFu, s, off);
        if (tx == 0) g_e[m0 + ty * 8 + i] = s;
    }
}

// ---------------- kernel 2: per-column online-softmax scan -> (a_t, b_t) ----------------
// C_t = a_t * C_{t-1} + b_t * H_t  where a_t = s_{t-1}*alpha_t/s_t, b_t = p_t/s_t
__global__ void k_scan() {
    int n = blockIdx.x * blockDim.x + threadIdx.x;   // 0..1023
    float m = -INFINITY, s = 0.0f;
    for (int t = 0; t < T_DIM; ++t) {
        float e  = g_e[t * N_DIM + n];
        float mn = fmaxf(m, e);
        float al = __expf(m - mn);       // exp(-inf) = 0 on first step
        float p  = __expf(e - mn);
        float sn = s * al + p;
        float inv = 1.0f / sn;
        g_a[t * N_DIM + n] = s * al * inv;
        g_b[t * N_DIM + n] = p * inv;
        m = mn; s = sn;
    }
}

// ---------------- kernel 3: streaming recurrence apply ----------------
// One block per column n (1024 blocks), one thread per d (256 threads).
__global__ __launch_bounds__(256) void k_apply(
    const float* __restrict__ H, float* __restrict__ out)
{
    const int n = blockIdx.x;
    const int d = threadIdx.x;
    float c = 0.0f;
    #pragma unroll 4
    for (int t = 0; t < T_DIM; ++t) {
        int   idx = t * N_DIM + n;
        float a   = g_a[idx];
        float b   = g_b[idx];
        float hv  = __ldg(&H[(size_t)idx * D_DIM + d]);
        c = fmaf(a, c, b * hv);
        out[(size_t)idx * D_DIM + d] = c;
    }
}

// ---------------- launch ----------------
extern "C" void kernel_launch(void* const* d_in, const int* in_sizes, int n_in,
                              void* d_out, int out_size) {
    const float* H       = (const float*)d_in[0];   // (T,N,D)
    const float* fc_w    = (const float*)d_in[1];   // (D,D)
    const float* fc_b    = (const float*)d_in[2];   // (D,)
    const float* score_w = (const float*)d_in[3];   // (D,)
    float* out = (float*)d_out;                      // (T,N,D)

    k_transpose<<<dim3(8, 8), dim3(32, 8)>>>(fc_w);
    k_score<<<TN / BM, 256>>>(H, fc_b, score_w);
    k_scan<<<4, 256>>>();
    k_apply<<<N_DIM, D_DIM>>>(H, out);
}

// round 4
// speedup vs baseline: 1.9583x; 1.9583x over previous
#include <cuda_runtime.h>
#include <cuda_bf16.h>
#include <cstdint>
#include <cmath>

// Problem dims (fixed per reference)
#define T_DIM 512
#define N_DIM 1024
#define D_DIM 256
#define TN    (T_DIM * N_DIM)

// ---------------- device scratch (static, no allocations) ----------------
__device__ float g_e[TN];
__device__ float g_a[TN];
__device__ float g_b[TN];
__device__ __nv_bfloat16 g_bhi[D_DIM * D_DIM];  // fc_w hi bf16, [e][d] (K-major)
__device__ __nv_bfloat16 g_blo[D_DIM * D_DIM];  // fc_w lo bf16

// ---------------- small helpers ----------------
__device__ __forceinline__ uint32_t smem_u32(const void* p) {
    uint32_t a;
    asm("{ .reg .u64 t; cvta.to.shared.u64 t, %1; cvt.u32.u64 %0, t; }" : "=r"(a) : "l"(p));
    return a;
}
__device__ __forceinline__ void cp16(uint32_t dst, const void* src) {
    asm volatile("cp.async.cg.shared.global [%0], [%1], 16;" :: "r"(dst), "l"(src));
}
#define CP_COMMIT() asm volatile("cp.async.commit_group;" ::: "memory")
#define CP_WAIT0()  asm volatile("cp.async.wait_group 0;" ::: "memory")

#define LDSM_X4(r0, r1, r2, r3, addr) \
    asm volatile("ldmatrix.sync.aligned.m8n8.x4.shared.b16 {%0,%1,%2,%3}, [%4];" \
                 : "=r"(r0), "=r"(r1), "=r"(r2), "=r"(r3) : "r"(addr))
#define LDSM_X2(r0, r1, addr) \
    asm volatile("ldmatrix.sync.aligned.m8n8.x2.shared.b16 {%0,%1}, [%2];" \
                 : "=r"(r0), "=r"(r1) : "r"(addr))
#define MMA_BF16(d, a0, a1, a2, a3, b0, b1) \
    asm volatile("mma.sync.aligned.m16n8k16.row.col.f32.bf16.bf16.f32 " \
                 "{%0,%1,%2,%3},{%4,%5,%6,%7},{%8,%9},{%0,%1,%2,%3};" \
                 : "+f"((d)[0]), "+f"((d)[1]), "+f"((d)[2]), "+f"((d)[3]) \
                 : "r"(a0), "r"(a1), "r"(a2), "r"(a3), "r"(b0), "r"(b1))

// accurate tanh (fast-math-proof): 1 - 2/(e^{2x}+1), saturates correctly
__device__ __forceinline__ float tanh_acc(float x) {
    float ex = __expf(2.0f * x);
    return 1.0f - 2.0f / (ex + 1.0f);
}

// ---------------- kernel 0: split fc_w into bf16 hi/lo ----------------
__global__ void k_bconv(const float* __restrict__ w) {
    int i = blockIdx.x * 256 + threadIdx.x;
    float x = w[i];
    __nv_bfloat16 hi = __float2bfloat16(x);
    g_bhi[i] = hi;
    g_blo[i] = __float2bfloat16(x - __bfloat162float(hi));
}

// ---------------- kernel 1: scoring GEMM via mma.sync (split bf16) ----------------
// Block: 256 thr, tile M=64 x N=256, K in 8 chunks of 32, 2-stage pipeline.
// acc = Ah*Bh + Al*Bh + Ah*Bl  (fp32 acc, residual ~2^-16)
#define BM       64
#define BK       32
#define ASTRIDE  80                         // 64B data + 16B pad per row
#define A_BYTES  (64 * ASTRIDE)             // 5120
#define B_BYTES  (256 * ASTRIDE)            // 20480
#define STAGE    (2 * A_BYTES + 2 * B_BYTES)  // 51200
#define OFF_CONST (2 * STAGE)               // 102400
#define SMEM_TOTAL (OFF_CONST + 2 * 256 * 4)  // 104448

__global__ __launch_bounds__(256, 2)
void k_score(const float* __restrict__ H,
             const float* __restrict__ fc_b,
             const float* __restrict__ score_w)
{
    extern __shared__ char smem[];
    const uint32_t sbase = smem_u32(smem);
    float* s_bias = (float*)(smem + OFF_CONST);
    float* s_sw   = (float*)(smem + OFF_CONST + 1024);

    const int tid   = threadIdx.x;
    const int wid   = tid >> 5;
    const int lane  = tid & 31;
    const int warpM = wid & 3;      // 16-row slab
    const int warpN = wid >> 2;     // 128-col half
    const int m0    = blockIdx.x * BM;

    s_bias[tid] = fc_b[tid];        // tid in [0,256)
    s_sw[tid]   = score_w[tid];

    float acc[64];                  // 16 n-tiles x 4
    #pragma unroll
    for (int i = 0; i < 64; ++i) acc[i] = 0.0f;

    // per-thread load roles
    const int arow = tid >> 2;      // A: row 0..63
    const int aseg = tid & 3;       // A: 8-float segment within 32-k chunk

    // ---- helper lambdas ----
    auto load_B_async = [&](int st, int kc) {
        uint32_t bh = sbase + st * STAGE + 2 * A_BYTES;
        uint32_t bl = bh + B_BYTES;
        const char* ph = (const char*)g_bhi;
        const char* pl = (const char*)g_blo;
        #pragma unroll
        for (int i = 0; i < 4; ++i) {
            int cid = tid + i * 256;          // 0..1023
            int row = cid >> 2;               // 0..255
            int seg = cid & 3;
            size_t gb = (size_t)(row * D_DIM + kc * BK + seg * 8) * 2;
            uint32_t so = (uint32_t)(row * ASTRIDE + seg * 16);
            cp16(bh + so, ph + gb);
            cp16(bl + so, pl + gb);
        }
    };
    auto load_A_regs = [&](int kc, float4& r0, float4& r1) {
        const float* p = &H[(size_t)(m0 + arow) * D_DIM + kc * BK + aseg * 8];
        r0 = *(const float4*)p;
        r1 = *(const float4*)(p + 4);
    };
    auto store_A = [&](int st, float4 r0, float4 r1) {
        float v[8] = {r0.x, r0.y, r0.z, r0.w, r1.x, r1.y, r1.z, r1.w};
        uint32_t uh[4], ul[4];
        #pragma unroll
        for (int j = 0; j < 4; ++j) {
            __nv_bfloat16 h0 = __float2bfloat16(v[2*j]);
            __nv_bfloat16 h1 = __float2bfloat16(v[2*j+1]);
            float l0 = v[2*j]   - __bfloat162float(h0);
            float l1 = v[2*j+1] - __bfloat162float(h1);
            __nv_bfloat162 hh = __nv_bfloat162(h0, h1);
            __nv_bfloat162 ll = __nv_bfloat162(__float2bfloat16(l0), __float2bfloat16(l1));
            uh[j] = *(uint32_t*)&hh;
            ul[j] = *(uint32_t*)&ll;
        }
        char* ah = smem + st * STAGE + arow * ASTRIDE + aseg * 16;
        *(uint4*)ah             = make_uint4(uh[0], uh[1], uh[2], uh[3]);
        *(uint4*)(ah + A_BYTES) = make_uint4(ul[0], ul[1], ul[2], ul[3]);
    };
    auto compute = [&](int st) {
        uint32_t a_hi = sbase + st * STAGE + warpM * 16 * ASTRIDE;
        uint32_t b_hi = sbase + st * STAGE + 2 * A_BYTES;
        uint32_t b_lo = b_hi + B_BYTES;
        #pragma unroll
        for (int ks = 0; ks < 2; ++ks) {
            uint32_t aoff = (lane & 15) * ASTRIDE + ks * 32 + (lane >> 4) * 16;
            uint32_t ah0, ah1, ah2, ah3, al0, al1, al2, al3;
            LDSM_X4(ah0, ah1, ah2, ah3, a_hi + aoff);
            LDSM_X4(al0, al1, al2, al3, a_hi + A_BYTES + aoff);
            #pragma unroll
            for (int nt = 0; nt < 16; ++nt) {
                uint32_t brow = (uint32_t)(warpN * 128 + nt * 8 + (lane & 7));
                uint32_t boff = brow * ASTRIDE + ks * 32 + ((lane >> 3) & 1) * 16;
                uint32_t bh0, bh1, bl0, bl1;
                LDSM_X2(bh0, bh1, b_hi + boff);
                LDSM_X2(bl0, bl1, b_lo + boff);
                float* d = &acc[nt * 4];
                MMA_BF16(d, ah0, ah1, ah2, ah3, bh0, bh1);
                MMA_BF16(d, al0, al1, al2, al3, bh0, bh1);
                MMA_BF16(d, ah0, ah1, ah2, ah3, bl0, bl1);
            }
        }
    };

    // ---- pipeline ----
    {
        load_B_async(0, 0);
        CP_COMMIT();
        float4 r0, r1;
        load_A_regs(0, r0, r1);
        store_A(0, r0, r1);
        CP_WAIT0();
        __syncthreads();
    }
    float4 p0, p1;
    #pragma unroll
    for (int kc = 0; kc < 8; ++kc) {
        int st = kc & 1;
        if (kc < 7) {
            load_B_async(st ^ 1, kc + 1);
            CP_COMMIT();
            load_A_regs(kc + 1, p0, p1);
        }
        compute(st);
        if (kc < 7) {
            store_A(st ^ 1, p0, p1);
            CP_WAIT0();
        }
        __syncthreads();
    }

    // ---- epilogue: bias + tanh + dot(score_w), 4-lane reduce ----
    float e0 = 0.0f, e1 = 0.0f;
    #pragma unroll
    for (int nt = 0; nt < 16; ++nt) {
        int col = warpN * 128 + nt * 8 + (lane & 3) * 2;
        float b0 = s_bias[col], b1 = s_bias[col + 1];
        float w0 = s_sw[col],   w1 = s_sw[col + 1];
        e0 = fmaf(tanh_acc(acc[nt*4+0] + b0), w0, e0);
        e0 = fmaf(tanh_acc(acc[nt*4+1] + b1), w1, e0);
        e1 = fmaf(tanh_acc(acc[nt*4+2] + b0), w0, e1);
        e1 = fmaf(tanh_acc(acc[nt*4+3] + b1), w1, e1);
    }
    e0 += __shfl_xor_sync(0xFFFFFFFFu, e0, 1);
    e0 += __shfl_xor_sync(0xFFFFFFFFu, e0, 2);
    e1 += __shfl_xor_sync(0xFFFFFFFFu, e1, 1);
    e1 += __shfl_xor_sync(0xFFFFFFFFu, e1, 2);
    if ((lane & 3) == 0) {
        int row = m0 + warpM * 16 + (lane >> 2);
        // two warps (warpN=0,1) produce the same row's partial over disjoint cols
        atomicAdd(&g_e[row], e0);
        atomicAdd(&g_e[row + 8], e1);
    }
}

// zero g_e before k_score (atomicAdd accumulation across the two col-halves)
__global__ void k_zero_e() {
    int i = blockIdx.x * 256 + threadIdx.x;
    g_e[i] = 0.0f;
}

// ---------------- kernel 2: per-column online-softmax scan -> (a_t, b_t) ----------------
__global__ void k_scan() {
    int n = blockIdx.x * blockDim.x + threadIdx.x;   // 0..1023
    float m = -INFINITY, s = 0.0f;
    for (int t = 0; t < T_DIM; ++t) {
        float e  = g_e[t * N_DIM + n];
        float mn = fmaxf(m, e);
        float al = __expf(m - mn);
        float p  = __expf(e - mn);
        float sn = s * al + p;
        float inv = 1.0f / sn;
        g_a[t * N_DIM + n] = s * al * inv;
        g_b[t * N_DIM + n] = p * inv;
        m = mn; s = sn;
    }
}

// ---------------- kernel 3: streaming recurrence apply (float4) ----------------
__global__ __launch_bounds__(256) void k_apply(
    const float* __restrict__ H, float* __restrict__ out)
{
    const int n  = blockIdx.x * 4 + (threadIdx.x >> 6);
    const int d4 = threadIdx.x & 63;
    float4 c = make_float4(0.f, 0.f, 0.f, 0.f);
    #pragma unroll 4
    for (int t = 0; t < T_DIM; ++t) {
        int idx = t * N_DIM + n;
        float a = g_a[idx];
        float b = g_b[idx];
        float4 h = *(const float4*)&H[(size_t)idx * D_DIM + d4 * 4];
        c.x = fmaf(a, c.x, b * h.x);
        c.y = fmaf(a, c.y, b * h.y);
        c.z = fmaf(a, c.z, b * h.z);
        c.w = fmaf(a, c.w, b * h.w);
        *(float4*)&out[(size_t)idx * D_DIM + d4 * 4] = c;
    }
}

// ---------------- launch ----------------
extern "C" void kernel_launch(void* const* d_in, const int* in_sizes, int n_in,
                              void* d_out, int out_size) {
    const float* H       = (const float*)d_in[0];
    const float* fc_w    = (const float*)d_in[1];
    const float* fc_b    = (const float*)d_in[2];
    const float* score_w = (const float*)d_in[3];
    float* out = (float*)d_out;

    cudaFuncSetAttribute(k_score, cudaFuncAttributeMaxDynamicSharedMemorySize, SMEM_TOTAL);

    k_bconv<<<D_DIM * D_DIM / 256, 256>>>(fc_w);
    k_zero_e<<<TN / 256, 256>>>();
    k_score<<<TN / BM, 256, SMEM_TOTAL>>>(H, fc_b, score_w);
    k_scan<<<4, 256>>>();
    k_apply<<<N_DIM / 4, 256>>>(H, out);
}

// round 5
// speedup vs baseline: 2.4908x; 1.2719x over previous
#include <cuda_runtime.h>
#include <cuda_bf16.h>
#include <cstdint>
#include <cmath>

// Problem dims (fixed per reference)
#define T_DIM 512
#define N_DIM 1024
#define D_DIM 256
#define TN    (T_DIM * N_DIM)

// ---------------- device scratch (static, no allocations) ----------------
__device__ float g_e[TN];
__device__ float g_a[TN];
__device__ float g_b[TN];
__device__ __nv_bfloat16 g_bhi[D_DIM * D_DIM];  // fc_w hi bf16, [e][d] (K-major)
__device__ __nv_bfloat16 g_blo[D_DIM * D_DIM];  // fc_w lo bf16

// ---------------- small helpers ----------------
__device__ __forceinline__ uint32_t smem_u32(const void* p) {
    uint32_t a;
    asm("{ .reg .u64 t; cvta.to.shared.u64 t, %1; cvt.u32.u64 %0, t; }" : "=r"(a) : "l"(p));
    return a;
}
__device__ __forceinline__ void cp16(uint32_t dst, const void* src) {
    asm volatile("cp.async.cg.shared.global [%0], [%1], 16;" :: "r"(dst), "l"(src));
}
#define CP_COMMIT() asm volatile("cp.async.commit_group;" ::: "memory")
#define CP_WAIT0()  asm volatile("cp.async.wait_group 0;" ::: "memory")

#define LDSM_X4(r0, r1, r2, r3, addr) \
    asm volatile("ldmatrix.sync.aligned.m8n8.x4.shared.b16 {%0,%1,%2,%3}, [%4];" \
                 : "=r"(r0), "=r"(r1), "=r"(r2), "=r"(r3) : "r"(addr))
#define LDSM_X2(r0, r1, addr) \
    asm volatile("ldmatrix.sync.aligned.m8n8.x2.shared.b16 {%0,%1}, [%2];" \
                 : "=r"(r0), "=r"(r1) : "r"(addr))
#define MMA_BF16(d, a0, a1, a2, a3, b0, b1) \
    asm volatile("mma.sync.aligned.m16n8k16.row.col.f32.bf16.bf16.f32 " \
                 "{%0,%1,%2,%3},{%4,%5,%6,%7},{%8,%9},{%0,%1,%2,%3};" \
                 : "+f"((d)[0]), "+f"((d)[1]), "+f"((d)[2]), "+f"((d)3[0-3]) )
#undef MMA_BF16
#define MMA_BF16(d, a0, a1, a2, a3, b0, b1) \
    asm volatile("mma.sync.aligned.m16n8k16.row.col.f32.bf16.bf16.f32 " \
                 "{%0,%1,%2,%3},{%4,%5,%6,%7},{%8,%9},{%0,%1,%2,%3};" \
                 : "+f"((d)[0]), "+f"((d)[1]), "+f"((d)[2]), "+f"((d)[3]) \
                 : "r"(a0), "r"(a1), "r"(a2), "r"(a3), "r"(b0), "r"(b1))

// accurate tanh (fast-math-proof): 1 - 2/(e^{2x}+1), saturates correctly
__device__ __forceinline__ float tanh_acc(float x) {
    float ex = __expf(2.0f * x);
    return 1.0f - 2.0f / (ex + 1.0f);
}

// ---------------- kernel 0: split fc_w into bf16 hi/lo ----------------
__global__ void k_bconv(const float* __restrict__ w) {
    int i = blockIdx.x * 256 + threadIdx.x;
    float x = w[i];
    __nv_bfloat16 hi = __float2bfloat16(x);
    g_bhi[i] = hi;
    g_blo[i] = __float2bfloat16(x - __bfloat162float(hi));
}

// ---------------- kernel 1: scoring GEMM via mma.sync (split bf16) ----------------
// Block: 256 thr (8 warps), tile M=64 x N=256; warp tile Mw=64 x Nw=32.
// K in 8 chunks of 32, 2-stage cp.async pipeline.
// acc = Ah*Bh + Al*Bh + Ah*Bl  (fp32 acc, residual ~2^-16)
#define BM       64
#define BK       32
#define ASTRIDE  80                           // 64B data + 16B pad per row
#define A_BYTES  (64 * ASTRIDE)               // 5120
#define B_BYTES  (256 * ASTRIDE)              // 20480
#define STAGE    (2 * A_BYTES + 2 * B_BYTES)  // 51200
#define OFF_CONST (2 * STAGE)                 // 102400
#define SMEM_TOTAL (OFF_CONST + 2 * 256 * 4)  // 104448

__global__ __launch_bounds__(256, 2)
void k_score(const float* __restrict__ H,
             const float* __restrict__ fc_b,
             const float* __restrict__ score_w)
{
    extern __shared__ char smem[];
    const uint32_t sbase = smem_u32(smem);
    float* s_bias = (float*)(smem + OFF_CONST);
    float* s_sw   = (float*)(smem + OFF_CONST + 1024);
    float* s_part = (float*)smem;             // reused after last compute (8*64 floats)

    const int tid  = threadIdx.x;
    const int wid  = tid >> 5;                // warp owns cols [wid*32, wid*32+32)
    const int lane = tid & 31;
    const int m0   = blockIdx.x * BM;

    s_bias[tid] = fc_b[tid];
    s_sw[tid]   = score_w[tid];

    float acc[64];                            // [mt 0..3][nt 0..3][4]
    #pragma unroll
    for (int i = 0; i < 64; ++i) acc[i] = 0.0f;

    const int arow = tid >> 2;                // A loader: row 0..63
    const int aseg = tid & 3;                 // 8-float segment within 32-k chunk

    auto load_B_async = [&](int st, int kc) {
        uint32_t bh = sbase + st * STAGE + 2 * A_BYTES;
        uint32_t bl = bh + B_BYTES;
        const char* ph = (const char*)g_bhi;
        const char* pl = (const char*)g_blo;
        #pragma unroll
        for (int i = 0; i < 4; ++i) {
            int cid = tid + i * 256;          // 0..1023
            int row = cid >> 2;               // 0..255
            int seg = cid & 3;
            size_t gb = (size_t)(row * D_DIM + kc * BK + seg * 8) * 2;
            uint32_t so = (uint32_t)(row * ASTRIDE + seg * 16);
            cp16(bh + so, ph + gb);
            cp16(bl + so, pl + gb);
        }
    };
    auto load_A_regs = [&](int kc, float4& r0, float4& r1) {
        const float* p = &H[(size_t)(m0 + arow) * D_DIM + kc * BK + aseg * 8];
        r0 = *(const float4*)p;
        r1 = *(const float4*)(p + 4);
    };
    auto store_A = [&](int st, float4 r0, float4 r1) {
        float v[8] = {r0.x, r0.y, r0.z, r0.w, r1.x, r1.y, r1.z, r1.w};
        uint32_t uh[4], ul[4];
        #pragma unroll
        for (int j = 0; j < 4; ++j) {
            __nv_bfloat16 h0 = __float2bfloat16(v[2*j]);
            __nv_bfloat16 h1 = __float2bfloat16(v[2*j+1]);
            float l0 = v[2*j]   - __bfloat162float(h0);
            float l1 = v[2*j+1] - __bfloat162float(h1);
            __nv_bfloat162 hh = __nv_bfloat162(h0, h1);
            __nv_bfloat162 ll = __nv_bfloat162(__float2bfloat16(l0), __float2bfloat16(l1));
            uh[j] = *(uint32_t*)&hh;
            ul[j] = *(uint32_t*)&ll;
        }
        char* ah = smem + st * STAGE + arow * ASTRIDE + aseg * 16;
        *(uint4*)ah             = make_uint4(uh[0], uh[1], uh[2], uh[3]);
        *(uint4*)(ah + A_BYTES) = make_uint4(ul[0], ul[1], ul[2], ul[3]);
    };
    auto compute = [&](int st) {
        uint32_t a_base = sbase + st * STAGE;
        uint32_t b_hi   = a_base + 2 * A_BYTES;
        uint32_t b_lo   = b_hi + B_BYTES;
        #pragma unroll
        for (int ks = 0; ks < 2; ++ks) {
            // load B fragments for this warp's 32 cols (4 n-tiles), hi+lo
            uint32_t bh[4][2], bl[4][2];
            #pragma unroll
            for (int nt = 0; nt < 4; ++nt) {
                uint32_t brow = (uint32_t)(wid * 32 + nt * 8 + (lane & 7));
                uint32_t boff = brow * ASTRIDE + ks * 32 + ((lane >> 3) & 1) * 16;
                LDSM_X2(bh[nt][0], bh[nt][1], b_hi + boff);
                LDSM_X2(bl[nt][0], bl[nt][1], b_lo + boff);
            }
            #pragma unroll
            for (int mt = 0; mt < 4; ++mt) {
                uint32_t aoff = (uint32_t)((mt * 16 + (lane & 15)) * ASTRIDE
                                           + ks * 32 + (lane >> 4) * 16);
                uint32_t ah0, ah1, ah2, ah3, al0, al1, al2, al3;
                LDSM_X4(ah0, ah1, ah2, ah3, a_base + aoff);
                LDSM_X4(al0, al1, al2, al3, a_base + A_BYTES + aoff);
                #pragma unroll
                for (int nt = 0; nt < 4; ++nt) {
                    float* d = &acc[(mt * 4 + nt) * 4];
                    MMA_BF16(d, ah0, ah1, ah2, ah3, bh[nt][0], bh[nt][1]);
                    MMA_BF16(d, al0, al1, al2, al3, bh[nt][0], bh[nt][1]);
                    MMA_BF16(d, ah0, ah1, ah2, ah3, bl[nt][0], bl[nt][1]);
                }
            }
        }
    };

    // ---- pipeline ----
    {
        load_B_async(0, 0);
        CP_COMMIT();
        float4 r0, r1;
        load_A_regs(0, r0, r1);
        store_A(0, r0, r1);
        CP_WAIT0();
        __syncthreads();
    }
    float4 p0, p1;
    #pragma unroll
    for (int kc = 0; kc < 8; ++kc) {
        int st = kc & 1;
        if (kc < 7) {
            load_B_async(st ^ 1, kc + 1);
            CP_COMMIT();
            load_A_regs(kc + 1, p0, p1);
        }
        compute(st);
        if (kc < 7) {
            store_A(st ^ 1, p0, p1);
            CP_WAIT0();
        }
        __syncthreads();
    }

    // ---- epilogue: bias + tanh + dot(score_w); smem cross-warp reduce ----
    #pragma unroll
    for (int mt = 0; mt < 4; ++mt) {
        float e0 = 0.0f, e1 = 0.0f;
        #pragma unroll
        for (int nt = 0; nt < 4; ++nt) {
            int col = wid * 32 + nt * 8 + (lane & 3) * 2;
            float b0 = s_bias[col], b1 = s_bias[col + 1];
            float w0 = s_sw[col],   w1 = s_sw[col + 1];
            float* d = &acc[(mt * 4 + nt) * 4];
            e0 = fmaf(tanh_acc(d[0] + b0), w0, e0);
            e0 = fmaf(tanh_acc(d[1] + b1), w1, e0);
            e1 = fmaf(tanh_acc(d[2] + b0), w0, e1);
            e1 = fmaf(tanh_acc(d[3] + b1), w1, e1);
        }
        e0 += __shfl_xor_sync(0xFFFFFFFFu, e0, 1);
        e0 += __shfl_xor_sync(0xFFFFFFFFu, e0, 2);
        e1 += __shfl_xor_sync(0xFFFFFFFFu, e1, 1);
        e1 += __shfl_xor_sync(0xFFFFFFFFu, e1, 2);
        if ((lane & 3) == 0) {
            int r = mt * 16 + (lane >> 2);
            s_part[wid * 64 + r]     = e0;
            s_part[wid * 64 + r + 8] = e1;
        }
    }
    __syncthreads();
    if (tid < 64) {
        float s = 0.0f;
        #pragma unroll
        for (int w = 0; w < 8; ++w) s += s_part[w * 64 + tid];
        g_e[m0 + tid] = s;
    }
}

// ---------------- kernel 2: parallel online-softmax scan (warp per column) ----------------
// lane l owns t in [l*16, l*16+16); monoid (m,s) combine via shfl scan; rewalk emits a,b.
__global__ __launch_bounds__(256) void k_scan() {
    const int wid  = threadIdx.x >> 5;
    const int lane = threadIdx.x & 31;
    const int n    = blockIdx.x * 8 + wid;      // 128 blocks x 8 warps = 1024 cols
    const int t0   = lane * 16;

    float ev[16];
    #pragma unroll
    for (int k = 0; k < 16; ++k) ev[k] = g_e[(t0 + k) * N_DIM + n];

    // local segment reduce -> (m, s)
    float m = -INFINITY, s = 0.0f;
    #pragma unroll
    for (int k = 0; k < 16; ++k) {
        float e  = ev[k];
        float mn = fmaxf(m, e);
        s = s * __expf(m - mn) + __expf(e - mn);
        m = mn;
    }
    // inclusive warp scan with softmax-state combine
    float im = m, is = s;
    #pragma unroll
    for (int off = 1; off < 32; off <<= 1) {
        float om = __shfl_up_sync(0xFFFFFFFFu, im, off);
        float os = __shfl_up_sync(0xFFFFFFFFu, is, off);
        if (lane >= off) {
            float mn = fmaxf(om, im);
            is = os * __expf(om - mn) + is * __expf(im - mn);
            im = mn;
        }
    }
    // exclusive prefix
    float Em = __shfl_up_sync(0xFFFFFFFFu, im, 1);
    float Es = __shfl_up_sync(0xFFFFFFFFu, is, 1);
    if (lane == 0) { Em = -INFINITY; Es = 0.0f; }

    // rewalk: serial recurrence from the exclusive prefix state
    float mc = Em, sc = Es;
    #pragma unroll
    for (int k = 0; k < 16; ++k) {
        float e   = ev[k];
        float mn  = fmaxf(mc, e);
        float al  = __expf(mc - mn);             // exp(-inf)=0 on first step
        float p   = __expf(e - mn);
        float sn  = sc * al + p;
        float inv = 1.0f / sn;
        int idx = (t0 + k) * N_DIM + n;
        g_a[idx] = sc * al * inv;
        g_b[idx] = p * inv;
        mc = mn; sc = sn;
    }
}

// ---------------- kernel 3: streaming recurrence apply (float4) ----------------
__global__ __launch_bounds__(256) void k_apply(
    const float* __restrict__ H, float* __restrict__ out)
{
    const int n  = blockIdx.x * 4 + (threadIdx.x >> 6);
    const int d4 = threadIdx.x & 63;
    float4 c = make_float4(0.f, 0.f, 0.f, 0.f);
    #pragma unroll 4
    for (int t = 0; t < T_DIM; ++t) {
        int idx = t * N_DIM + n;
        float a = g_a[idx];
        float b = g_b[idx];
        float4 h = *(const float4*)&H[(size_t)idx * D_DIM + d4 * 4];
        c.x = fmaf(a, c.x, b * h.x);
        c.y = fmaf(a, c.y, b * h.y);
        c.z = fmaf(a, c.z, b * h.z);
        c.w = fmaf(a, c.w, b * h.w);
        *(float4*)&out[(size_t)idx * D_DIM + d4 * 4] = c;
    }
}

// ---------------- launch ----------------
extern "C" void kernel_launch(void* const* d_in, const int* in_sizes, int n_in,
                              void* d_out, int out_size) {
    const float* H       = (const float*)d_in[0];
    const float* fc_w    = (const float*)d_in[1];
    const float* fc_b    = (const float*)d_in[2];
    const float* score_w = (const float*)d_in[3];
    float* out = (float*)d_out;

    cudaFuncSetAttribute(k_score, cudaFuncAttributeMaxDynamicSharedMemorySize, SMEM_TOTAL);

    k_bconv<<<D_DIM * D_DIM / 256, 256>>>(fc_w);
    k_score<<<TN / BM, 256, SMEM_TOTAL>>>(H, fc_b, score_w);
    k_scan<<<128, 256>>>();
    k_apply<<<N_DIM / 4, 256>>>(H, out);
}

// round 6
// speedup vs baseline: 2.5703x; 1.0319x over previous
#include <cuda_runtime.h>
#include <cuda_bf16.h>
#include <cstdint>
#include <cmath>

// Problem dims (fixed per reference)
#define T_DIM 512
#define N_DIM 1024
#define D_DIM 256
#define TN    (T_DIM * N_DIM)

// ---------------- device scratch (static, no allocations) ----------------
__device__ float g_e[TN];
__device__ float g_a[TN];
__device__ float g_b[TN];
__device__ __nv_bfloat16 g_bhi[D_DIM * D_DIM];  // fc_w hi bf16, [e][d] (K-major)
__device__ __nv_bfloat16 g_blo[D_DIM * D_DIM];  // fc_w lo bf16

// ---------------- small helpers ----------------
__device__ __forceinline__ uint32_t smem_u32(const void* p) {
    uint32_t a;
    asm("{ .reg .u64 t; cvta.to.shared.u64 t, %1; cvt.u32.u64 %0, t; }" : "=r"(a) : "l"(p));
    return a;
}
__device__ __forceinline__ void cp16(uint32_t dst, const void* src) {
    asm volatile("cp.async.cg.shared.global [%0], [%1], 16;" :: "r"(dst), "l"(src));
}
#define CP_COMMIT() asm volatile("cp.async.commit_group;" ::: "memory")
#define CP_WAIT0()  asm volatile("cp.async.wait_group 0;" ::: "memory")

#define LDSM_X4(r0, r1, r2, r3, addr) \
    asm volatile("ldmatrix.sync.aligned.m8n8.x4.shared.b16 {%0,%1,%2,%3}, [%4];" \
                 : "=r"(r0), "=r"(r1), "=r"(r2), "=r"(r3) : "r"(addr))
#define LDSM_X2(r0, r1, addr) \
    asm volatile("ldmatrix.sync.aligned.m8n8.x2.shared.b16 {%0,%1}, [%2];" \
                 : "=r"(r0), "=r"(r1) : "r"(addr))
#define MMA_BF16(d, a0, a1, a2, a3, b0, b1) \
    asm volatile("mma.sync.aligned.m16n8k16.row.col.f32.bf16.bf16.f32 " \
                 "{%0,%1,%2,%3},{%4,%5,%6,%7},{%8,%9},{%0,%1,%2,%3};" \
                 : "+f"((d)[0]), "+f"((d)[1]), "+f"((d)[2]), "+f"((d)[3]) \
                 : "r"(a0), "r"(a1), "r"(a2), "r"(a3), "r"(b0), "r"(b1))

// accurate tanh (fast-math-proof): 1 - 2/(e^{2x}+1), saturates correctly
__device__ __forceinline__ float tanh_acc(float x) {
    float ex = __expf(2.0f * x);
    return 1.0f - 2.0f / (ex + 1.0f);
}

// ---------------- kernel 0: split fc_w into bf16 hi/lo ----------------
__global__ void k_bconv(const float* __restrict__ w) {
    int i = blockIdx.x * 256 + threadIdx.x;
    float x = w[i];
    __nv_bfloat16 hi = __float2bfloat16(x);
    g_bhi[i] = hi;
    g_blo[i] = __float2bfloat16(x - __bfloat162float(hi));
}

// ---------------- kernel 1: scoring GEMM via mma.sync (split bf16) ----------------
// Block: 256 thr (8 warps), tile M=64 x N=256; warp tile Mw=64 x Nw=32.
// K in 8 chunks of 32, 2-stage cp.async pipeline.
// acc = Ah*Bh + Al*Bh + Ah*Bl  (fp32 acc, residual ~2^-16)
#define BM       64
#define BK       32
#define ASTRIDE  80                           // 64B data + 16B pad per row
#define A_BYTES  (64 * ASTRIDE)               // 5120
#define B_BYTES  (256 * ASTRIDE)              // 20480
#define STAGE    (2 * A_BYTES + 2 * B_BYTES)  // 51200
#define OFF_CONST (2 * STAGE)                 // 102400
#define SMEM_TOTAL (OFF_CONST + 2 * 256 * 4)  // 104448

__global__ __launch_bounds__(256, 2)
void k_score(const float* __restrict__ H,
             const float* __restrict__ fc_b,
             const float* __restrict__ score_w)
{
    extern __shared__ char smem[];
    const uint32_t sbase = smem_u32(smem);
    float* s_bias = (float*)(smem + OFF_CONST);
    float* s_sw   = (float*)(smem + OFF_CONST + 1024);
    float* s_part = (float*)smem;             // reused after last compute (8*64 floats)

    const int tid  = threadIdx.x;
    const int wid  = tid >> 5;                // warp owns cols [wid*32, wid*32+32)
    const int lane = tid & 31;
    const int m0   = blockIdx.x * BM;

    s_bias[tid] = fc_b[tid];
    s_sw[tid]   = score_w[tid];

    float acc[64];                            // [mt 0..3][nt 0..3][4]
    #pragma unroll
    for (int i = 0; i < 64; ++i) acc[i] = 0.0f;

    const int arow = tid >> 2;                // A loader: row 0..63
    const int aseg = tid & 3;                 // 8-float segment within 32-k chunk

    auto load_B_async = [&](int st, int kc) {
        uint32_t bh = sbase + st * STAGE + 2 * A_BYTES;
        uint32_t bl = bh + B_BYTES;
        const char* ph = (const char*)g_bhi;
        const char* pl = (const char*)g_blo;
        #pragma unroll
        for (int i = 0; i < 4; ++i) {
            int cid = tid + i * 256;          // 0..1023
            int row = cid >> 2;               // 0..255
            int seg = cid & 3;
            size_t gb = (size_t)(row * D_DIM + kc * BK + seg * 8) * 2;
            uint32_t so = (uint32_t)(row * ASTRIDE + seg * 16);
            cp16(bh + so, ph + gb);
            cp16(bl + so, pl + gb);
        }
    };
    auto load_A_regs = [&](int kc, float4& r0, float4& r1) {
        const float* p = &H[(size_t)(m0 + arow) * D_DIM + kc * BK + aseg * 8];
        r0 = *(const float4*)p;
        r1 = *(const float4*)(p + 4);
    };
    auto store_A = [&](int st, float4 r0, float4 r1) {
        float v[8] = {r0.x, r0.y, r0.z, r0.w, r1.x, r1.y, r1.z, r1.w};
        uint32_t uh[4], ul[4];
        #pragma unroll
        for (int j = 0; j < 4; ++j) {
            __nv_bfloat16 h0 = __float2bfloat16(v[2*j]);
            __nv_bfloat16 h1 = __float2bfloat16(v[2*j+1]);
            float l0 = v[2*j]   - __bfloat162float(h0);
            float l1 = v[2*j+1] - __bfloat162float(h1);
            __nv_bfloat162 hh = __nv_bfloat162(h0, h1);
            __nv_bfloat162 ll = __nv_bfloat162(__float2bfloat16(l0), __float2bfloat16(l1));
            uh[j] = *(uint32_t*)&hh;
            ul[j] = *(uint32_t*)&ll;
        }
        char* ah = smem + st * STAGE + arow * ASTRIDE + aseg * 16;
        *(uint4*)ah             = make_uint4(uh[0], uh[1], uh[2], uh[3]);
        *(uint4*)(ah + A_BYTES) = make_uint4(ul[0], ul[1], ul[2], ul[3]);
    };
    auto compute = [&](int st) {
        uint32_t a_base = sbase + st * STAGE;
        uint32_t b_hi   = a_base + 2 * A_BYTES;
        uint32_t b_lo   = b_hi + B_BYTES;
        #pragma unroll
        for (int ks = 0; ks < 2; ++ks) {
            uint32_t bh[4][2], bl[4][2];
            #pragma unroll
            for (int nt = 0; nt < 4; ++nt) {
                uint32_t brow = (uint32_t)(wid * 32 + nt * 8 + (lane & 7));
                uint32_t boff = brow * ASTRIDE + ks * 32 + ((lane >> 3) & 1) * 16;
                LDSM_X2(bh[nt][0], bh[nt][1], b_hi + boff);
                LDSM_X2(bl[nt][0], bl[nt][1], b_lo + boff);
            }
            #pragma unroll
            for (int mt = 0; mt < 4; ++mt) {
                uint32_t aoff = (uint32_t)((mt * 16 + (lane & 15)) * ASTRIDE
                                           + ks * 32 + (lane >> 4) * 16);
                uint32_t ah0, ah1, ah2, ah3, al0, al1, al2, al3;
                LDSM_X4(ah0, ah1, ah2, ah3, a_base + aoff);
                LDSM_X4(al0, al1, al2, al3, a_base + A_BYTES + aoff);
                #pragma unroll
                for (int nt = 0; nt < 4; ++nt) {
                    float* d = &acc[(mt * 4 + nt) * 4];
                    MMA_BF16(d, ah0, ah1, ah2, ah3, bh[nt][0], bh[nt][1]);
                    MMA_BF16(d, al0, al1, al2, al3, bh[nt][0], bh[nt][1]);
                    MMA_BF16(d, ah0, ah1, ah2, ah3, bl[nt][0], bl[nt][1]);
                }
            }
        }
    };

    // ---- pipeline ----
    {
        load_B_async(0, 0);
        CP_COMMIT();
        float4 r0, r1;
        load_A_regs(0, r0, r1);
        store_A(0, r0, r1);
        CP_WAIT0();
        __syncthreads();
    }
    float4 p0, p1;
    #pragma unroll
    for (int kc = 0; kc < 8; ++kc) {
        int st = kc & 1;
        if (kc < 7) {
            load_B_async(st ^ 1, kc + 1);
            CP_COMMIT();
            load_A_regs(kc + 1, p0, p1);
        }
        compute(st);
        if (kc < 7) {
            store_A(st ^ 1, p0, p1);
            CP_WAIT0();
        }
        __syncthreads();
    }

    // ---- epilogue: bias + tanh + dot(score_w); smem cross-warp reduce ----
    #pragma unroll
    for (int mt = 0; mt < 4; ++mt) {
        float e0 = 0.0f, e1 = 0.0f;
        #pragma unroll
        for (int nt = 0; nt < 4; ++nt) {
            int col = wid * 32 + nt * 8 + (lane & 3) * 2;
            float b0 = s_bias[col], b1 = s_bias[col + 1];
            float w0 = s_sw[col],   w1 = s_sw[col + 1];
            float* d = &acc[(mt * 4 + nt) * 4];
            e0 = fmaf(tanh_acc(d[0] + b0), w0, e0);
            e0 = fmaf(tanh_acc(d[1] + b1), w1, e0);
            e1 = fmaf(tanh_acc(d[2] + b0), w0, e1);
            e1 = fmaf(tanh_acc(d[3] + b1), w1, e1);
        }
        e0 += __shfl_xor_sync(0xFFFFFFFFu, e0, 1);
        e0 += __shfl_xor_sync(0xFFFFFFFFu, e0, 2);
        e1 += __shfl_xor_sync(0xFFFFFFFFu, e1, 1);
        e1 += __shfl_xor_sync(0xFFFFFFFFu, e1, 2);
        if ((lane & 3) == 0) {
            int r = mt * 16 + (lane >> 2);
            s_part[wid * 64 + r]     = e0;
            s_part[wid * 64 + r + 8] = e1;
        }
    }
    __syncthreads();
    if (tid < 64) {
        float s = 0.0f;
        #pragma unroll
        for (int w = 0; w < 8; ++w) s += s_part[w * 64 + tid];
        g_e[m0 + tid] = s;
    }
}

// ---------------- kernel 2: parallel online-softmax scan (warp per column) ----------------
__global__ __launch_bounds__(256) void k_scan() {
    const int wid  = threadIdx.x >> 5;
    const int lane = threadIdx.x & 31;
    const int n    = blockIdx.x * 8 + wid;      // 128 blocks x 8 warps = 1024 cols
    const int t0   = lane * 16;

    float ev[16];
    #pragma unroll
    for (int k = 0; k < 16; ++k) ev[k] = g_e[(t0 + k) * N_DIM + n];

    float m = -INFINITY, s = 0.0f;
    #pragma unroll
    for (int k = 0; k < 16; ++k) {
        float e  = ev[k];
        float mn = fmaxf(m, e);
        s = s * __expf(m - mn) + __expf(e - mn);
        m = mn;
    }
    float im = m, is = s;
    #pragma unroll
    for (int off = 1; off < 32; off <<= 1) {
        float om = __shfl_up_sync(0xFFFFFFFFu, im, off);
        float os = __shfl_up_sync(0xFFFFFFFFu, is, off);
        if (lane >= off) {
            float mn = fmaxf(om, im);
            is = os * __expf(om - mn) + is * __expf(im - mn);
            im = mn;
        }
    }
    float Em = __shfl_up_sync(0xFFFFFFFFu, im, 1);
    float Es = __shfl_up_sync(0xFFFFFFFFu, is, 1);
    if (lane == 0) { Em = -INFINITY; Es = 0.0f; }

    float mc = Em, sc = Es;
    #pragma unroll
    for (int k = 0; k < 16; ++k) {
        float e   = ev[k];
        float mn  = fmaxf(mc, e);
        float al  = __expf(mc - mn);
        float p   = __expf(e - mn);
        float sn  = sc * al + p;
        float inv = 1.0f / sn;
        int idx = (t0 + k) * N_DIM + n;
        g_a[idx] = sc * al * inv;
        g_b[idx] = p * inv;
        mc = mn; sc = sn;
    }
}

// ---------------- kernel 3: streaming recurrence apply ----------------
// One block (64 thr) per column n: 1024 blocks. t unrolled x4 with batched
// independent loads (4 float4 H + 8 scalars in flight) before the fma chain.
__global__ __launch_bounds__(64) void k_apply(
    const float* __restrict__ H, float* __restrict__ out)
{
    const int n  = blockIdx.x;
    const int d4 = threadIdx.x;                     // 0..63
    const size_t base = (size_t)n * D_DIM + d4 * 4;
    const size_t tstep = (size_t)N_DIM * D_DIM;     // per-t stride in floats

    float4 c = make_float4(0.f, 0.f, 0.f, 0.f);
    #pragma unroll 2
    for (int t = 0; t < T_DIM; t += 4) {
        const int ia = t * N_DIM + n;
        float a0 = g_a[ia],             b0 = g_b[ia];
        float a1 = g_a[ia + N_DIM],     b1 = g_b[ia + N_DIM];
        float a2 = g_a[ia + 2 * N_DIM], b2 = g_b[ia + 2 * N_DIM];
        float a3 = g_a[ia + 3 * N_DIM], b3 = g_b[ia + 3 * N_DIM];
        float4 h0 = *(const float4*)&H[base + (size_t)(t + 0) * tstep];
        float4 h1 = *(const float4*)&H[base + (size_t)(t + 1) * tstep];
        float4 h2 = *(const float4*)&H[base + (size_t)(t + 2) * tstep];
        float4 h3 = *(const float4*)&H[base + (size_t)(t + 3) * tstep];

        c.x = fmaf(a0, c.x, b0 * h0.x); c.y = fmaf(a0, c.y, b0 * h0.y);
        c.z = fmaf(a0, c.z, b0 * h0.z); c.w = fmaf(a0, c.w, b0 * h0.w);
        *(float4*)&out[base + (size_t)(t + 0) * tstep] = c;

        c.x = fmaf(a1, c.x, b1 * h1.x); c.y = fmaf(a1, c.y, b1 * h1.y);
        c.z = fmaf(a1, c.z, b1 * h1.z); c.w = fmaf(a1, c.w, b1 * h1.w);
        *(float4*)&out[base + (size_t)(t + 1) * tstep] = c;

        c.x = fmaf(a2, c.x, b2 * h2.x); c.y = fmaf(a2, c.y, b2 * h2.y);
        c.z = fmaf(a2, c.z, b2 * h2.z); c.w = fmaf(a2, c.w, b2 * h2.w);
        *(float4*)&out[base + (size_t)(t + 2) * tstep] = c;

        c.x = fmaf(a3, c.x, b3 * h3.x); c.y = fmaf(a3, c.y, b3 * h3.y);
        c.z = fmaf(a3, c.z, b3 * h3.z); c.w = fmaf(a3, c.w, b3 * h3.w);
        *(float4*)&out[base + (size_t)(t + 3) * tstep] = c;
    }
}

// ---------------- launch ----------------
extern "C" void kernel_launch(void* const* d_in, const int* in_sizes, int n_in,
                              void* d_out, int out_size) {
    const float* H       = (const float*)d_in[0];
    const float* fc_w    = (const float*)d_in[1];
    const float* fc_b    = (const float*)d_in[2];
    const float* score_w = (const float*)d_in[3];
    float* out = (float*)d_out;

    cudaFuncSetAttribute(k_score, cudaFuncAttributeMaxDynamicSharedMemorySize, SMEM_TOTAL);

    k_bconv<<<D_DIM * D_DIM / 256, 256>>>(fc_w);
    k_score<<<TN / BM, 256, SMEM_TOTAL>>>(H, fc_b, score_w);
    k_scan<<<128, 256>>>();
    k_apply<<<N_DIM, 64>>>(H, out);
}

// round 7
// speedup vs baseline: 2.7013x; 1.0510x over previous
#include <cuda_runtime.h>
#include <cuda_bf16.h>
#include <cstdint>
#include <cmath>

// Problem dims (fixed per reference)
#define T_DIM 512
#define N_DIM 1024
#define D_DIM 256
#define TN    (T_DIM * N_DIM)

// ---------------- device scratch (static, no allocations) ----------------
__device__ float g_e[TN];
__device__ float g_a[TN];
__device__ float g_b[TN];
__device__ __nv_bfloat16 g_bhi[D_DIM * D_DIM];  // fc_w hi bf16, [e][d] (K-major)
__device__ __nv_bfloat16 g_blo[D_DIM * D_DIM];  // fc_w lo bf16

// ---------------- small helpers ----------------
__device__ __forceinline__ uint32_t smem_u32(const void* p) {
    uint32_t a;
    asm("{ .reg .u64 t; cvta.to.shared.u64 t, %1; cvt.u32.u64 %0, t; }" : "=r"(a) : "l"(p));
    return a;
}
__device__ __forceinline__ void cp16(uint32_t dst, const void* src) {
    asm volatile("cp.async.cg.shared.global [%0], [%1], 16;" :: "r"(dst), "l"(src));
}
#define CP_COMMIT() asm volatile("cp.async.commit_group;" ::: "memory")
#define CP_WAIT0()  asm volatile("cp.async.wait_group 0;" ::: "memory")

#define LDSM_X4(r0, r1, r2, r3, addr) \
    asm volatile("ldmatrix.sync.aligned.m8n8.x4.shared.b16 {%0,%1,%2,%3}, [%4];" \
                 : "=r"(r0), "=r"(r1), "=r"(r2), "=r"(r3) : "r"(addr))
#define LDSM_X2(r0, r1, addr) \
    asm volatile("ldmatrix.sync.aligned.m8n8.x2.shared.b16 {%0,%1}, [%2];" \
                 : "=r"(r0), "=r"(r1) : "r"(addr))
#define MMA_BF16(d, a0, a1, a2, a3, b0, b1) \
    asm volatile("mma.sync.aligned.m16n8k16.row.col.f32.bf16.bf16.f32 " \
                 "{%0,%1,%2,%3},{%4,%5,%6,%7},{%8,%9},{%0,%1,%2,%3};" \
                 : "+f"((d)[0]), "+f"((d)[1]), "+f"((d)[2]), "+f"((d)[3]) \
                 : "r"(a0), "r"(a1), "r"(a2), "r"(a3), "r"(b0), "r"(b1))

// accurate tanh (fast-math-proof): 1 - 2/(e^{2x}+1), saturates correctly
__device__ __forceinline__ float tanh_acc(float x) {
    float ex = __expf(2.0f * x);
    return 1.0f - 2.0f / (ex + 1.0f);
}

// ---------------- kernel 0: split fc_w into bf16 hi/lo ----------------
__global__ void k_bconv(const float* __restrict__ w) {
    int i = blockIdx.x * 256 + threadIdx.x;
    float x = w[i];
    __nv_bfloat16 hi = __float2bfloat16(x);
    g_bhi[i] = hi;
    g_blo[i] = __float2bfloat16(x - __bfloat162float(hi));
}

// ---------------- kernel 1: scoring GEMM via mma.sync (split bf16) ----------------
// Block: 512 thr (16 warps), tile M=128 x N=256; warp tile Mw=64 x Nw=32
// (warpM = wid>>3 selects 64-row half, warpN = wid&7 selects 32-col group).
// K in 8 chunks of 32, 2-stage cp.async pipeline.
// acc = Ah*Bh + Al*Bh + Ah*Bl  (fp32 acc, residual ~2^-16)
#define BM       128
#define BK       32
#define ASTRIDE  80                           // 64B data + 16B pad per row
#define A_BYTES  (128 * ASTRIDE)              // 10240
#define B_BYTES  (256 * ASTRIDE)              // 20480
#define STAGE    (2 * A_BYTES + 2 * B_BYTES)  // 61440
#define OFF_CONST (2 * STAGE)                 // 122880
#define SMEM_TOTAL (OFF_CONST + 2 * 256 * 4)  // 124928

__global__ __launch_bounds__(512, 1)
void k_score(const float* __restrict__ H,
             const float* __restrict__ fc_b,
             const float* __restrict__ score_w)
{
    extern __shared__ char smem[];
    const uint32_t sbase = smem_u32(smem);
    float* s_bias = (float*)(smem + OFF_CONST);
    float* s_sw   = (float*)(smem + OFF_CONST + 1024);
    float* s_part = (float*)smem;             // reused after last compute (8*128 floats)

    const int tid   = threadIdx.x;
    const int wid   = tid >> 5;
    const int lane  = tid & 31;
    const int warpM = wid >> 3;               // 0..1 : 64-row half
    const int warpN = wid & 7;                // 0..7 : 32-col group
    const int m0    = blockIdx.x * BM;

    if (tid < 256) { s_bias[tid] = fc_b[tid]; s_sw[tid] = score_w[tid]; }

    float acc[64];                            // [mt 0..3][nt 0..3][4]
    #pragma unroll
    for (int i = 0; i < 64; ++i) acc[i] = 0.0f;

    const int arow = tid >> 2;                // A loader: row 0..127
    const int aseg = tid & 3;                 // 8-float segment within 32-k chunk

    auto load_B_async = [&](int st, int kc) {
        uint32_t bh = sbase + st * STAGE + 2 * A_BYTES;
        uint32_t bl = bh + B_BYTES;
        const char* ph = (const char*)g_bhi;
        const char* pl = (const char*)g_blo;
        #pragma unroll
        for (int i = 0; i < 2; ++i) {
            int cid = tid + i * 512;          // 0..1023
            int row = cid >> 2;               // 0..255
            int seg = cid & 3;
            size_t gb = (size_t)(row * D_DIM + kc * BK + seg * 8) * 2;
            uint32_t so = (uint32_t)(row * ASTRIDE + seg * 16);
            cp16(bh + so, ph + gb);
            cp16(bl + so, pl + gb);
        }
    };
    auto load_A_regs = [&](int kc, float4& r0, float4& r1) {
        const float* p = &H[(size_t)(m0 + arow) * D_DIM + kc * BK + aseg * 8];
        r0 = *(const float4*)p;
        r1 = *(const float4*)(p + 4);
    };
    auto store_A = [&](int st, float4 r0, float4 r1) {
        float v[8] = {r0.x, r0.y, r0.z, r0.w, r1.x, r1.y, r1.z, r1.w};
        uint32_t uh[4], ul[4];
        #pragma unroll
        for (int j = 0; j < 4; ++j) {
            __nv_bfloat16 h0 = __float2bfloat16(v[2*j]);
            __nv_bfloat16 h1 = __float2bfloat16(v[2*j+1]);
            float l0 = v[2*j]   - __bfloat162float(h0);
            float l1 = v[2*j+1] - __bfloat162float(h1);
            __nv_bfloat162 hh = __nv_bfloat162(h0, h1);
            __nv_bfloat162 ll = __nv_bfloat162(__float2bfloat16(l0), __float2bfloat16(l1));
            uh[j] = *(uint32_t*)&hh;
            ul[j] = *(uint32_t*)&ll;
        }
        char* ah = smem + st * STAGE + arow * ASTRIDE + aseg * 16;
        *(uint4*)ah             = make_uint4(uh[0], uh[1], uh[2], uh[3]);
        *(uint4*)(ah + A_BYTES) = make_uint4(ul[0], ul[1], ul[2], ul[3]);
    };
    auto compute = [&](int st) {
        uint32_t a_base = sbase + st * STAGE;
        uint32_t b_hi   = a_base + 2 * A_BYTES;
        uint32_t b_lo   = b_hi + B_BYTES;
        #pragma unroll
        for (int ks = 0; ks < 2; ++ks) {
            uint32_t bh[4][2], bl[4][2];
            #pragma unroll
            for (int nt = 0; nt < 4; ++nt) {
                uint32_t brow = (uint32_t)(warpN * 32 + nt * 8 + (lane & 7));
                uint32_t boff = brow * ASTRIDE + ks * 32 + ((lane >> 3) & 1) * 16;
                LDSM_X2(bh[nt][0], bh[nt][1], b_hi + boff);
                LDSM_X2(bl[nt][0], bl[nt][1], b_lo + boff);
            }
            #pragma unroll
            for (int mt = 0; mt < 4; ++mt) {
                uint32_t arf = (uint32_t)(warpM * 64 + mt * 16 + (lane & 15));
                uint32_t aoff = arf * ASTRIDE + ks * 32 + (lane >> 4) * 16;
                uint32_t ah0, ah1, ah2, ah3, al0, al1, al2, al3;
                LDSM_X4(ah0, ah1, ah2, ah3, a_base + aoff);
                LDSM_X4(al0, al1, al2, al3, a_base + A_BYTES + aoff);
                #pragma unroll
                for (int nt = 0; nt < 4; ++nt) {
                    float* d = &acc[(mt * 4 + nt) * 4];
                    MMA_BF16(d, ah0, ah1, ah2, ah3, bh[nt][0], bh[nt][1]);
                    MMA_BF16(d, al0, al1, al2, al3, bh[nt][0], bh[nt][1]);
                    MMA_BF16(d, ah0, ah1, ah2, ah3, bl[nt][0], bl[nt][1]);
                }
            }
        }
    };

    // ---- pipeline ----
    {
        load_B_async(0, 0);
        CP_COMMIT();
        float4 r0, r1;
        load_A_regs(0, r0, r1);
        store_A(0, r0, r1);
        CP_WAIT0();
        __syncthreads();
    }
    float4 p0, p1;
    #pragma unroll
    for (int kc = 0; kc < 8; ++kc) {
        int st = kc & 1;
        if (kc < 7) {
            load_B_async(st ^ 1, kc + 1);
            CP_COMMIT();
            load_A_regs(kc + 1, p0, p1);
        }
        compute(st);
        if (kc < 7) {
            store_A(st ^ 1, p0, p1);
            CP_WAIT0();
        }
        __syncthreads();
    }

    // ---- epilogue: bias + tanh + dot(score_w); smem cross-warp reduce ----
    #pragma unroll
    for (int mt = 0; mt < 4; ++mt) {
        float e0 = 0.0f, e1 = 0.0f;
        #pragma unroll
        for (int nt = 0; nt < 4; ++nt) {
            int col = warpN * 32 + nt * 8 + (lane & 3) * 2;
            float b0 = s_bias[col], b1 = s_bias[col + 1];
            float w0 = s_sw[col],   w1 = s_sw[col + 1];
            float* d = &acc[(mt * 4 + nt) * 4];
            e0 = fmaf(tanh_acc(d[0] + b0), w0, e0);
            e0 = fmaf(tanh_acc(d[1] + b1), w1, e0);
            e1 = fmaf(tanh_acc(d[2] + b0), w0, e1);
            e1 = fmaf(tanh_acc(d[3] + b1), w1, e1);
        }
        e0 += __shfl_xor_sync(0xFFFFFFFFu, e0, 1);
        e0 += __shfl_xor_sync(0xFFFFFFFFu, e0, 2);
        e1 += __shfl_xor_sync(0xFFFFFFFFu, e1, 1);
        e1 += __shfl_xor_sync(0xFFFFFFFFu, e1, 2);
        if ((lane & 3) == 0) {
            int r = warpM * 64 + mt * 16 + (lane >> 2);
            s_part[warpN * 128 + r]     = e0;
            s_part[warpN * 128 + r + 8] = e1;
        }
    }
    __syncthreads();
    if (tid < 128) {
        float s = 0.0f;
        #pragma unroll
        for (int w = 0; w < 8; ++w) s += s_part[w * 128 + tid];
        g_e[m0 + tid] = s;
    }
}

// ---------------- kernel 2: parallel online-softmax scan (warp per column) ----------------
__global__ __launch_bounds__(256) void k_scan() {
    const int wid  = threadIdx.x >> 5;
    const int lane = threadIdx.x & 31;
    const int n    = blockIdx.x * 8 + wid;      // 128 blocks x 8 warps = 1024 cols
    const int t0   = lane * 16;

    float ev[16];
    #pragma unroll
    for (int k = 0; k < 16; ++k) ev[k] = g_e[(t0 + k) * N_DIM + n];

    float m = -INFINITY, s = 0.0f;
    #pragma unroll
    for (int k = 0; k < 16; ++k) {
        float e  = ev[k];
        float mn = fmaxf(m, e);
        s = s * __expf(m - mn) + __expf(e - mn);
        m = mn;
    }
    float im = m, is = s;
    #pragma unroll
    for (int off = 1; off < 32; off <<= 1) {
        float om = __shfl_up_sync(0xFFFFFFFFu, im, off);
        float os = __shfl_up_sync(0xFFFFFFFFu, is, off);
        if (lane >= off) {
            float mn = fmaxf(om, im);
            is = os * __expf(om - mn) + is * __expf(im - mn);
            im = mn;
        }
    }
    float Em = __shfl_up_sync(0xFFFFFFFFu, im, 1);
    float Es = __shfl_up_sync(0xFFFFFFFFu, is, 1);
    if (lane == 0) { Em = -INFINITY; Es = 0.0f; }

    float mc = Em, sc = Es;
    #pragma unroll
    for (int k = 0; k < 16; ++k) {
        float e   = ev[k];
        float mn  = fmaxf(mc, e);
        float al  = __expf(mc - mn);
        float p   = __expf(e - mn);
        float sn  = sc * al + p;
        float inv = 1.0f / sn;
        int idx = (t0 + k) * N_DIM + n;
        g_a[idx] = sc * al * inv;
        g_b[idx] = p * inv;
        mc = mn; sc = sn;
    }
}

// ---------------- kernel 3: streaming recurrence apply ----------------
// One block (64 thr) per column n. t unrolled x8 with ALL loads batched
// before the dependent fma chain: 8 float4 H (128 B) + 16 scalars in flight.
__global__ __launch_bounds__(64) void k_apply(
    const float* __restrict__ H, float* __restrict__ out)
{
    const int n  = blockIdx.x;
    const int d4 = threadIdx.x;                     // 0..63
    const size_t base  = (size_t)n * D_DIM + d4 * 4;
    const size_t tstep = (size_t)N_DIM * D_DIM;     // per-t stride in floats

    float4 c = make_float4(0.f, 0.f, 0.f, 0.f);
    for (int t = 0; t < T_DIM; t += 8) {
        const int ia = t * N_DIM + n;
        float a[8], b[8];
        #pragma unroll
        for (int j = 0; j < 8; ++j) {
            a[j] = g_a[ia + j * N_DIM];
            b[j] = g_b[ia + j * N_DIM];
        }
        float4 h[8];
        #pragma unroll
        for (int j = 0; j < 8; ++j)
            h[j] = *(const float4*)&H[base + (size_t)(t + j) * tstep];
        #pragma unroll
        for (int j = 0; j < 8; ++j) {
            c.x = fmaf(a[j], c.x, b[j] * h[j].x);
            c.y = fmaf(a[j], c.y, b[j] * h[j].y);
            c.z = fmaf(a[j], c.z, b[j] * h[j].z);
            c.w = fmaf(a[j], c.w, b[j] * h[j].w);
            *(float4*)&out[base + (size_t)(t + j) * tstep] = c;
        }
    }
}

// ---------------- launch ----------------
extern "C" void kernel_launch(void* const* d_in, const int* in_sizes, int n_in,
                              void* d_out, int out_size) {
    const float* H       = (const float*)d_in[0];
    const float* fc_w    = (const float*)d_in[1];
    const float* fc_b    = (const float*)d_in[2];
    const float* score_w = (const float*)d_in[3];
    float* out = (float*)d_out;

    cudaFuncSetAttribute(k_score, cudaFuncAttributeMaxDynamicSharedMemorySize, SMEM_TOTAL);

    k_bconv<<<D_DIM * D_DIM / 256, 256>>>(fc_w);
    k_score<<<TN / BM, 512, SMEM_TOTAL>>>(H, fc_b, score_w);
    k_scan<<<128, 256>>>();
    k_apply<<<N_DIM, 64>>>(H, out);
}

// round 8
// speedup vs baseline: 2.7748x; 1.0272x over previous
#include <cuda_runtime.h>
#include <cuda_bf16.h>
#include <cstdint>
#include <cmath>

// Problem dims (fixed per reference)
#define T_DIM 512
#define N_DIM 1024
#define D_DIM 256
#define TN    (T_DIM * N_DIM)

// ---------------- device scratch (static, no allocations) ----------------
__device__ float g_e[TN];
__device__ float g_a[TN];
__device__ float g_b[TN];
__device__ __nv_bfloat16 g_bhi[D_DIM * D_DIM];  // fc_w hi bf16, [e][d] (K-major)
__device__ __nv_bfloat16 g_blo[D_DIM * D_DIM];  // fc_w lo bf16

// ---------------- small helpers ----------------
__device__ __forceinline__ uint32_t smem_u32(const void* p) {
    uint32_t a;
    asm("{ .reg .u64 t; cvta.to.shared.u64 t, %1; cvt.u32.u64 %0, t; }" : "=r"(a) : "l"(p));
    return a;
}
__device__ __forceinline__ void cp16(uint32_t dst, const void* src) {
    asm volatile("cp.async.cg.shared.global [%0], [%1], 16;" :: "r"(dst), "l"(src));
}
#define CP_COMMIT() asm volatile("cp.async.commit_group;" ::: "memory")
#define CP_WAIT0()  asm volatile("cp.async.wait_group 0;" ::: "memory")
#define CP_WAIT1()  asm volatile("cp.async.wait_group 1;" ::: "memory")

#define LDSM_X4(r0, r1, r2, r3, addr) \
    asm volatile("ldmatrix.sync.aligned.m8n8.x4.shared.b16 {%0,%1,%2,%3}, [%4];" \
                 : "=r"(r0), "=r"(r1), "=r"(r2), "=r"(r3) : "r"(addr))
#define LDSM_X2(r0, r1, addr) \
    asm volatile("ldmatrix.sync.aligned.m8n8.x2.shared.b16 {%0,%1}, [%2];" \
                 : "=r"(r0), "=r"(r1) : "r"(addr))
#define MMA_BF16(d, a0, a1, a2, a3, b0, b1) \
    asm volatile("mma.sync.aligned.m16n8k16.row.col.f32.bf16.bf16.f32 " \
                 "{%0,%1,%2,%3},{%4,%5,%6,%7},{%8,%9},{%0,%1,%2,%3};" \
                 : "+f"((d)[0]), "+f"((d)[1]), "+f"((d)[2]), "+f"((d)[3]) \
                 : "r"(a0), "r"(a1), "r"(a2), "r"(a3), "r"(b0), "r"(b1))

// accurate tanh (fast-math-proof): 1 - 2/(e^{2x}+1), saturates correctly
__device__ __forceinline__ float tanh_acc(float x) {
    float ex = __expf(2.0f * x);
    return 1.0f - 2.0f / (ex + 1.0f);
}

// ---------------- kernel 0: split fc_w into bf16 hi/lo ----------------
__global__ void k_bconv(const float* __restrict__ w) {
    int i = blockIdx.x * 256 + threadIdx.x;
    float x = w[i];
    __nv_bfloat16 hi = __float2bfloat16(x);
    g_bhi[i] = hi;
    g_blo[i] = __float2bfloat16(x - __bfloat162float(hi));
}

// ---------------- kernel 1: scoring GEMM via mma.sync (split bf16) ----------------
// Block: 512 thr (16 warps), tile M=128 x N=256; warp tile Mw=64 x Nw=32.
// K in 8 chunks of 32; 3-stage cp.async pipeline (wait_group 1 keeps the
// next chunk's B load in flight across the per-chunk sync).
// acc = Ah*Bh + Al*Bh + Ah*Bl  (fp32 acc, residual ~2^-16)
#define BM       128
#define BK       32
#define ASTRIDE  80                           // 64B data + 16B pad per row
#define A_BYTES  (128 * ASTRIDE)              // 10240
#define B_BYTES  (256 * ASTRIDE)              // 20480
#define STAGE    (2 * A_BYTES + 2 * B_BYTES)  // 61440
#define NSTAGE   3
#define OFF_CONST (NSTAGE * STAGE)            // 184320
#define SMEM_TOTAL (OFF_CONST + 2 * 256 * 4)  // 186368

__global__ __launch_bounds__(512, 1)
void k_score(const float* __restrict__ H,
             const float* __restrict__ fc_b,
             const float* __restrict__ score_w)
{
    extern __shared__ char smem[];
    const uint32_t sbase = smem_u32(smem);
    float* s_bias = (float*)(smem + OFF_CONST);
    float* s_sw   = (float*)(smem + OFF_CONST + 1024);
    float* s_part = (float*)smem;             // reused after last compute

    const int tid   = threadIdx.x;
    const int wid   = tid >> 5;
    const int lane  = tid & 31;
    const int warpM = wid >> 3;               // 0..1 : 64-row half
    const int warpN = wid & 7;                // 0..7 : 32-col group
    const int m0    = blockIdx.x * BM;

    if (tid < 256) { s_bias[tid] = fc_b[tid]; s_sw[tid] = score_w[tid]; }

    float acc[64];
    #pragma unroll
    for (int i = 0; i < 64; ++i) acc[i] = 0.0f;

    const int arow = tid >> 2;                // A loader: row 0..127
    const int aseg = tid & 3;                 // 8-float segment within 32-k chunk

    auto load_B_async = [&](int st, int kc) {
        uint32_t bh = sbase + st * STAGE + 2 * A_BYTES;
        uint32_t bl = bh + B_BYTES;
        const char* ph = (const char*)g_bhi;
        const char* pl = (const char*)g_blo;
        #pragma unroll
        for (int i = 0; i < 2; ++i) {
            int cid = tid + i * 512;          // 0..1023
            int row = cid >> 2;               // 0..255
            int seg = cid & 3;
            size_t gb = (size_t)(row * D_DIM + kc * BK + seg * 8) * 2;
            uint32_t so = (uint32_t)(row * ASTRIDE + seg * 16);
            cp16(bh + so, ph + gb);
            cp16(bl + so, pl + gb);
        }
    };
    auto load_A_regs = [&](int kc, float4& r0, float4& r1) {
        const float* p = &H[(size_t)(m0 + arow) * D_DIM + kc * BK + aseg * 8];
        r0 = *(const float4*)p;
        r1 = *(const float4*)(p + 4);
    };
    auto store_A = [&](int st, float4 r0, float4 r1) {
        float v[8] = {r0.x, r0.y, r0.z, r0.w, r1.x, r1.y, r1.z, r1.w};
        uint32_t uh[4], ul[4];
        #pragma unroll
        for (int j = 0; j < 4; ++j) {
            __nv_bfloat16 h0 = __float2bfloat16(v[2*j]);
            __nv_bfloat16 h1 = __float2bfloat16(v[2*j+1]);
            float l0 = v[2*j]   - __bfloat162float(h0);
            float l1 = v[2*j+1] - __bfloat162float(h1);
            __nv_bfloat162 hh = __nv_bfloat162(h0, h1);
            __nv_bfloat162 ll = __nv_bfloat162(__float2bfloat16(l0), __float2bfloat16(l1));
            uh[j] = *(uint32_t*)&hh;
            ul[j] = *(uint32_t*)&ll;
        }
        char* ah = smem + st * STAGE + arow * ASTRIDE + aseg * 16;
        *(uint4*)ah             = make_uint4(uh[0], uh[1], uh[2], uh[3]);
        *(uint4*)(ah + A_BYTES) = make_uint4(ul[0], ul[1], ul[2], ul[3]);
    };
    auto compute = [&](int st) {
        uint32_t a_base = sbase + st * STAGE;
        uint32_t b_hi   = a_base + 2 * A_BYTES;
        uint32_t b_lo   = b_hi + B_BYTES;
        #pragma unroll
        for (int ks = 0; ks < 2; ++ks) {
            uint32_t bh[4][2], bl[4][2];
            #pragma unroll
            for (int nt = 0; nt < 4; ++nt) {
                uint32_t brow = (uint32_t)(warpN * 32 + nt * 8 + (lane & 7));
                uint32_t boff = brow * ASTRIDE + ks * 32 + ((lane >> 3) & 1) * 16;
                LDSM_X2(bh[nt][0], bh[nt][1], b_hi + boff);
                LDSM_X2(bl[nt][0], bl[nt][1], b_lo + boff);
            }
            #pragma unroll
            for (int mt = 0; mt < 4; ++mt) {
                uint32_t arf = (uint32_t)(warpM * 64 + mt * 16 + (lane & 15));
                uint32_t aoff = arf * ASTRIDE + ks * 32 + (lane >> 4) * 16;
                uint32_t ah0, ah1, ah2, ah3, al0, al1, al2, al3;
                LDSM_X4(ah0, ah1, ah2, ah3, a_base + aoff);
                LDSM_X4(al0, al1, al2, al3, a_base + A_BYTES + aoff);
                #pragma unroll
                for (int nt = 0; nt < 4; ++nt) {
                    float* d = &acc[(mt * 4 + nt) * 4];
                    MMA_BF16(d, ah0, ah1, ah2, ah3, bh[nt][0], bh[nt][1]);
                    MMA_BF16(d, al0, al1, al2, al3, bh[nt][0], bh[nt][1]);
                    MMA_BF16(d, ah0, ah1, ah2, ah3, bl[nt][0], bl[nt][1]);
                }
            }
        }
    };

    // ---- prologue: chunks 0 and 1 into stages 0 and 1 ----
    {
        float4 r0, r1;
        load_B_async(0, 0); CP_COMMIT();
        load_A_regs(0, r0, r1); store_A(0, r0, r1);
        load_B_async(1, 1); CP_COMMIT();
        load_A_regs(1, r0, r1); store_A(1, r0, r1);
        CP_WAIT1();                       // chunk 0's B resident; chunk 1 in flight
        __syncthreads();
    }

    // ---- mainloop: 3-stage rotation ----
    #pragma unroll
    for (int kc = 0; kc < 8; ++kc) {
        const int st = kc % NSTAGE;
        float4 p0, p1;
        if (kc + 2 < 8) {
            const int st2 = (kc + 2) % NSTAGE;   // == (kc-1)%3, free after prev sync
            load_B_async(st2, kc + 2); CP_COMMIT();
            load_A_regs(kc + 2, p0, p1);
            compute(st);
            store_A(st2, p0, p1);
            CP_WAIT1();                   // next chunk resident; chunk kc+2 in flight
        } else {
            compute(st);
            CP_WAIT0();
        }
        __syncthreads();
    }

    // ---- epilogue: bias + tanh + dot(score_w); smem cross-warp reduce ----
    #pragma unroll
    for (int mt = 0; mt < 4; ++mt) {
        float e0 = 0.0f, e1 = 0.0f;
        #pragma unroll
        for (int nt = 0; nt < 4; ++nt) {
            int col = warpN * 32 + nt * 8 + (lane & 3) * 2;
            float b0 = s_bias[col], b1 = s_bias[col + 1];
            float w0 = s_sw[col],   w1 = s_sw[col + 1];
            float* d = &acc[(mt * 4 + nt) * 4];
            e0 = fmaf(tanh_acc(d[0] + b0), w0, e0);
            e0 = fmaf(tanh_acc(d[1] + b1), w1, e0);
            e1 = fmaf(tanh_acc(d[2] + b0), w0, e1);
            e1 = fmaf(tanh_acc(d[3] + b1), w1, e1);
        }
        e0 += __shfl_xor_sync(0xFFFFFFFFu, e0, 1);
        e0 += __shfl_xor_sync(0xFFFFFFFFu, e0, 2);
        e1 += __shfl_xor_sync(0xFFFFFFFFu, e1, 1);
        e1 += __shfl_xor_sync(0xFFFFFFFFu, e1, 2);
        if ((lane & 3) == 0) {
            int r = warpM * 64 + mt * 16 + (lane >> 2);
            s_part[warpN * 128 + r]     = e0;
            s_part[warpN * 128 + r + 8] = e1;
        }
    }
    __syncthreads();
    if (tid < 128) {
        float s = 0.0f;
        #pragma unroll
        for (int w = 0; w < 8; ++w) s += s_part[w * 128 + tid];
        g_e[m0 + tid] = s;
    }
}

// ---------------- kernel 2: parallel online-softmax scan (warp per column) ----------------
__global__ __launch_bounds__(256) void k_scan() {
    const int wid  = threadIdx.x >> 5;
    const int lane = threadIdx.x & 31;
    const int n    = blockIdx.x * 8 + wid;      // 128 blocks x 8 warps = 1024 cols
    const int t0   = lane * 16;

    float ev[16];
    #pragma unroll
    for (int k = 0; k < 16; ++k) ev[k] = g_e[(t0 + k) * N_DIM + n];

    float m = -INFINITY, s = 0.0f;
    #pragma unroll
    for (int k = 0; k < 16; ++k) {
        float e  = ev[k];
        float mn = fmaxf(m, e);
        s = s * __expf(m - mn) + __expf(e - mn);
        m = mn;
    }
    float im = m, is = s;
    #pragma unroll
    for (int off = 1; off < 32; off <<= 1) {
        float om = __shfl_up_sync(0xFFFFFFFFu, im, off);
        float os = __shfl_up_sync(0xFFFFFFFFu, is, off);
        if (lane >= off) {
            float mn = fmaxf(om, im);
            is = os * __expf(om - mn) + is * __expf(im - mn);
            im = mn;
        }
    }
    float Em = __shfl_up_sync(0xFFFFFFFFu, im, 1);
    float Es = __shfl_up_sync(0xFFFFFFFFu, is, 1);
    if (lane == 0) { Em = -INFINITY; Es = 0.0f; }

    float mc = Em, sc = Es;
    #pragma unroll
    for (int k = 0; k < 16; ++k) {
        float e   = ev[k];
        float mn  = fmaxf(mc, e);
        float al  = __expf(mc - mn);
        float p   = __expf(e - mn);
        float sn  = sc * al + p;
        float inv = 1.0f / sn;
        int idx = (t0 + k) * N_DIM + n;
        g_a[idx] = sc * al * inv;
        g_b[idx] = p * inv;
        mc = mn; sc = sn;
    }
}

// ---------------- kernel 3: streaming recurrence apply (scalar/thread) ----------------
// One block (256 thr) per column n; one thread per (n, d). 262144 threads total
// -> occupancy-driven latency hiding; 8 scalar H loads batched per unroll step.
__global__ __launch_bounds__(256) void k_apply(
    const float* __restrict__ H, float* __restrict__ out)
{
    const int n = blockIdx.x;
    const int d = threadIdx.x;                      // 0..255
    const size_t base  = (size_t)n * D_DIM + d;
    const size_t tstep = (size_t)N_DIM * D_DIM;     // per-t stride in floats

    float c = 0.0f;
    for (int t = 0; t < T_DIM; t += 8) {
        const int ia = t * N_DIM + n;
        float a[8], b[8], h[8];
        #pragma unroll
        for (int j = 0; j < 8; ++j) {
            a[j] = g_a[ia + j * N_DIM];             // uniform per block (broadcast)
            b[j] = g_b[ia + j * N_DIM];
        }
        #pragma unroll
        for (int j = 0; j < 8; ++j)
            h[j] = H[base + (size_t)(t + j) * tstep];
        #pragma unroll
        for (int j = 0; j < 8; ++j) {
            c = fmaf(a[j], c, b[j] * h[j]);
            out[base + (size_t)(t + j) * tstep] = c;
        }
    }
}

// ---------------- launch ----------------
extern "C" void kernel_launch(void* const* d_in, const int* in_sizes, int n_in,
                              void* d_out, int out_size) {
    const float* H       = (const float*)d_in[0];
    const float* fc_w    = (const float*)d_in[1];
    const float* fc_b    = (const float*)d_in[2];
    const float* score_w = (const float*)d_in[3];
    float* out = (float*)d_out;

    cudaFuncSetAttribute(k_score, cudaFuncAttributeMaxDynamicSharedMemorySize, SMEM_TOTAL);

    k_bconv<<<D_DIM * D_DIM / 256, 256>>>(fc_w);
    k_score<<<TN / BM, 512, SMEM_TOTAL>>>(H, fc_b, score_w);
    k_scan<<<128, 256>>>();
    k_apply<<<N_DIM, 256>>>(H, out);
}